// round 16
// baseline (speedup 1.0000x reference)
#include <cuda_runtime.h>
#include <cuda_bf16.h>
#include <math.h>
#include <cstdint>
#include <cstring>

// ---------------- problem constants ----------------
#define L       2048
#define BATCH   2
#define DM      768
#define DI      1536
#define DS      128
#define HD      64
#define NH      24
#define CONVD   1792
#define NPROJ   3352
#define NPAD    3456          // 27 * 128
#define M4      4096
#define CS      128
#define NCH     (L / CS)      // 16

// ---------------- scratch ----------------
__device__ float g_zx [2u * M4 * NPROJ];
__device__ float g_xBC[2u * M4 * CONVD];
__device__ float g_dt [2u * M4 * NH];
__device__ float g_dA [2u * M4 * NH];
__device__ float g_y  [2u * M4 * DI];
__device__ float g_cumP[2u * M4 * NH];
__device__ float g_lend  [96u * NCH * (HD * DS)];
__device__ float g_hcarry[96u * NCH * (HD * DS)];

__device__ __nv_bfloat16 g_Ah0[(size_t)M4 * DM],   g_Al0[(size_t)M4 * DM];   // linear (dir0 order)
__device__ __nv_bfloat16 g_Wh0[2u * NPAD * DM], g_Wl0[2u * NPAD * DM];
__device__ __nv_bfloat16 g_Ah1[2u * M4 * DI],   g_Al1[2u * M4 * DI];
__device__ __nv_bfloat16 g_Wh1[2u * DM * DI],   g_Wl1[2u * DM * DI];

// =====================================================================
// helpers
// =====================================================================
__device__ __forceinline__ uint32_t smem_u32(const void* p) {
    uint32_t a;
    asm("{ .reg .u64 t; cvta.to.shared.u64 t, %1; cvt.u32.u64 %0, t; }" : "=r"(a) : "l"(p));
    return a;
}
__device__ __forceinline__ uint32_t b2u(__nv_bfloat162 v) {
    uint32_t u; memcpy(&u, &v, 4); return u;
}
__device__ __forceinline__ void ldsm4(uint32_t& r0, uint32_t& r1, uint32_t& r2, uint32_t& r3,
                                      uint32_t addr) {
    asm volatile("ldmatrix.sync.aligned.m8n8.x4.shared.b16 {%0,%1,%2,%3}, [%4];"
        : "=r"(r0), "=r"(r1), "=r"(r2), "=r"(r3) : "r"(addr));
}
__device__ __forceinline__ void mma16816(float* c, const uint32_t* a, const uint32_t* b) {
    asm volatile(
        "mma.sync.aligned.m16n8k16.row.col.f32.bf16.bf16.f32 "
        "{%0,%1,%2,%3}, {%4,%5,%6,%7}, {%8,%9}, {%0,%1,%2,%3};"
        : "+f"(c[0]), "+f"(c[1]), "+f"(c[2]), "+f"(c[3])
        : "r"(a[0]), "r"(a[1]), "r"(a[2]), "r"(a[3]), "r"(b[0]), "r"(b[1]));
}
__device__ __forceinline__ void cpa16(uint32_t dst, const void* src) {
    asm volatile("cp.async.cg.shared.global [%0], [%1], 16;" :: "r"(dst), "l"(src));
}
__device__ __forceinline__ void split4(float4 v, uint2& h, uint2& l) {
    __nv_bfloat162 h0 = __float22bfloat162_rn(make_float2(v.x, v.y));
    __nv_bfloat162 h1 = __float22bfloat162_rn(make_float2(v.z, v.w));
    float2 f0 = __bfloat1622float2(h0), f1 = __bfloat1622float2(h1);
    __nv_bfloat162 l0 = __float22bfloat162_rn(make_float2(v.x - f0.x, v.y - f0.y));
    __nv_bfloat162 l1 = __float22bfloat162_rn(make_float2(v.z - f1.x, v.w - f1.y));
    h = make_uint2(b2u(h0), b2u(h1));
    l = make_uint2(b2u(l0), b2u(l1));
}
typedef unsigned long long u64t;
__device__ __forceinline__ u64t pack2(float a, float b) {
    u64t r; asm("mov.b64 %0, {%1, %2};" : "=l"(r) : "f"(a), "f"(b)); return r;
}
__device__ __forceinline__ void unpack2(u64t v, float& a, float& b) {
    asm("mov.b64 {%0, %1}, %2;" : "=f"(a), "=f"(b) : "l"(v));
}
__device__ __forceinline__ u64t fma2(u64t a, u64t b, u64t c) {
    u64t d; asm("fma.rn.f32x2 %0, %1, %2, %3;" : "=l"(d) : "l"(a), "l"(b), "l"(c)); return d;
}
__device__ __forceinline__ u64t mul2(u64t a, u64t b) {
    u64t d; asm("mul.rn.f32x2 %0, %1, %2;" : "=l"(d) : "l"(a), "l"(b)); return d;
}
__device__ __forceinline__ float fast_silu(float v) {
    return __fdividef(v, 1.f + __expf(-v));
}

// =====================================================================
// operand split kernels
// =====================================================================
__global__ void __launch_bounds__(256) split_x(const float* __restrict__ x)
{
    const int idx = blockIdx.x * 256 + threadIdx.x;   // over M4*(DM/4), linear
    if (idx >= M4 * (DM / 4)) return;
    const float4 v = *(const float4*)(x + (size_t)idx * 4);
    uint2 h, l; split4(v, h, l);
    *(uint2*)(g_Ah0 + (size_t)idx * 4) = h;
    *(uint2*)(g_Al0 + (size_t)idx * 4) = l;
}

__global__ void __launch_bounds__(256) split_w0(const float* __restrict__ w)
{
    const int idx = blockIdx.x * 256 + threadIdx.x;
    if (idx >= 2 * NPAD * (DM / 4)) return;
    const int k4 = idx % (DM / 4);
    const int rn = idx / (DM / 4);
    const int n  = rn % NPAD;
    const int dir = rn / NPAD;
    float4 v = make_float4(0.f, 0.f, 0.f, 0.f);
    if (n < NPROJ)
        v = *(const float4*)(w + ((size_t)dir * NPROJ + n) * DM + k4 * 4);
    uint2 h, l; split4(v, h, l);
    *(uint2*)(g_Wh0 + (size_t)rn * DM + k4 * 4) = h;
    *(uint2*)(g_Wl0 + (size_t)rn * DM + k4 * 4) = l;
}

__global__ void __launch_bounds__(256) split_w1(const float* __restrict__ w)
{
    const int idx = blockIdx.x * 256 + threadIdx.x;
    if (idx >= 2 * DM * (DI / 4)) return;
    const float4 v = *(const float4*)(w + (size_t)idx * 4);
    uint2 h, l; split4(v, h, l);
    *(uint2*)(g_Wh1 + (size_t)idx * 4) = h;
    *(uint2*)(g_Wl1 + (size_t)idx * 4) = l;
}

// =====================================================================
// in_proj GEMM; grid (27, 32, 2), BM=BN=128, 2-stage, 2 CTAs/SM.
// dir1 reads the linear A-split arrays with per-row flipped indexing.
// =====================================================================
#define GARR  10240
#define GSTG  (4 * GARR)
#define GSMEM (2 * GSTG)

__global__ void __launch_bounds__(256, 2) gemm0()
{
    extern __shared__ __align__(128) char smem[];
    const uint32_t sb = smem_u32(smem);

    const int tid  = threadIdx.x;
    const int wid  = tid >> 5;
    const int lane = tid & 31;
    const int n0   = blockIdx.x * 128;
    const int m0   = blockIdx.y * 128;
    const int dir0 = blockIdx.z;
    const int S    = DM / 32;

    const int arr = tid >> 6;
    const int rw0 = (tid & 63) * 2;
    const uint32_t sdst0 = sb + arr * GARR + rw0 * 80;

    const __nv_bfloat16* srcp;
    int rstr;
    if (arr < 2) {
        const __nv_bfloat16* base = arr ? g_Al0 : g_Ah0;
        const int m = m0 + rw0;
        if (dir0 == 0) {
            srcp = base + (size_t)m * DM;
            rstr = DM;
        } else {
            const int t  = m & (L - 1);
            const int sm = (m - t) + (L - 1 - t);
            srcp = base + (size_t)sm * DM;
            rstr = -DM;
        }
    } else {
        const __nv_bfloat16* base = (arr == 2) ? g_Wh0 : g_Wl0;
        srcp = base + ((size_t)dir0 * NPAD + n0 + rw0) * DM;
        rstr = DM;
    }

#define ISSUE0(s) do {                                                       \
        const int _s = (s);                                                  \
        const __nv_bfloat16* _p = srcp + _s * 32;                            \
        const uint32_t _dst = sdst0 + (_s & 1) * GSTG;                       \
        cpa16(_dst +  0, _p);                                                \
        cpa16(_dst + 16, _p + 8);                                            \
        cpa16(_dst + 32, _p + 16);                                           \
        cpa16(_dst + 48, _p + 24);                                           \
        cpa16(_dst + 80 +  0, _p + rstr);                                    \
        cpa16(_dst + 80 + 16, _p + rstr + 8);                                \
        cpa16(_dst + 80 + 32, _p + rstr + 16);                               \
        cpa16(_dst + 80 + 48, _p + rstr + 24);                               \
        asm volatile("cp.async.commit_group;" ::: "memory");                 \
    } while (0)

    float acc[4][4][4];
#pragma unroll
    for (int i = 0; i < 4; ++i)
#pragma unroll
        for (int j = 0; j < 4; ++j)
#pragma unroll
            for (int k = 0; k < 4; ++k) acc[i][j][k] = 0.f;

    const int wm  = (wid >> 2) * 64;
    const int wn  = (wid & 3) * 32;
    const int arl = (lane & 7) + ((lane >> 3) & 1) * 8;
    const int akb = (lane >> 4) * 16;
    const int brl = (lane & 7) + (lane >> 4) * 8;
    const int bkb = ((lane >> 3) & 1) * 16;

    ISSUE0(0);
    ISSUE0(1);

    for (int s = 0; s < S; ++s) {
        if (s == S - 1) asm volatile("cp.async.wait_group 0;" ::: "memory");
        else            asm volatile("cp.async.wait_group 1;" ::: "memory");
        __syncthreads();

        const uint32_t ub  = sb + (s & 1) * GSTG;
        const uint32_t uAh = ub;
        const uint32_t uAl = ub + GARR;
        const uint32_t uBh = ub + 2 * GARR;
        const uint32_t uBl = ub + 3 * GARR;

#pragma unroll
        for (int ks = 0; ks < 2; ++ks) {
            uint32_t ah[4][4], al_[4][4], bh[2][4], bl[2][4];
#pragma unroll
            for (int mf = 0; mf < 4; ++mf) {
                const uint32_t off = (uint32_t)(wm + mf * 16 + arl) * 80 + ks * 32 + akb;
                ldsm4(ah[mf][0],  ah[mf][1],  ah[mf][2],  ah[mf][3],  uAh + off);
                ldsm4(al_[mf][0], al_[mf][1], al_[mf][2], al_[mf][3], uAl + off);
            }
#pragma unroll
            for (int nf2 = 0; nf2 < 2; ++nf2) {
                const uint32_t off = (uint32_t)(wn + nf2 * 16 + brl) * 80 + ks * 32 + bkb;
                ldsm4(bh[nf2][0], bh[nf2][1], bh[nf2][2], bh[nf2][3], uBh + off);
                ldsm4(bl[nf2][0], bl[nf2][1], bl[nf2][2], bl[nf2][3], uBl + off);
            }
#pragma unroll
            for (int mf = 0; mf < 4; ++mf)
#pragma unroll
                for (int nf2 = 0; nf2 < 2; ++nf2)
#pragma unroll
                    for (int hf = 0; hf < 2; ++hf) {
                        float* c = acc[mf][nf2 * 2 + hf];
                        mma16816(c, ah[mf],  &bh[nf2][hf * 2]);
                        mma16816(c, ah[mf],  &bl[nf2][hf * 2]);
                        mma16816(c, al_[mf], &bh[nf2][hf * 2]);
                    }
        }
        __syncthreads();
        if (s + 2 < S) ISSUE0(s + 2);
    }
#undef ISSUE0

    const int g  = lane >> 2;
    const int tg = lane & 3;
#pragma unroll
    for (int mf = 0; mf < 4; ++mf)
#pragma unroll
        for (int nf = 0; nf < 4; ++nf) {
            const int mrow = m0 + wm + mf * 16 + g;
            const int ncol = n0 + wn + nf * 8 + tg * 2;
            const float* c = acc[mf][nf];
            if (ncol < NPROJ) {
                float* o0 = g_zx + ((size_t)(dir0 * M4 + mrow)) * NPROJ + ncol;
                float* o1 = g_zx + ((size_t)(dir0 * M4 + mrow + 8)) * NPROJ + ncol;
                o0[0] = c[0]; o0[1] = c[1];
                o1[0] = c[2]; o1[1] = c[3];
            }
        }
}

// =====================================================================
// out_proj GEMM (merged dirs): BM=64, BN=128, grid (6,64)=384 blocks,
// 3 CTAs/SM, K = 2 x DI accumulated in one pass; writes final output.
// =====================================================================
#define ARR_A64 5120
#define ARR_B1  10240
#define STG1    (2 * ARR_A64 + 2 * ARR_B1)
#define SMEM1   (2 * STG1)

__global__ void __launch_bounds__(256, 3) gemm1(float* __restrict__ Cg)
{
    extern __shared__ __align__(128) char smem[];
    const uint32_t sb = smem_u32(smem);

    const int tid  = threadIdx.x;
    const int wid  = tid >> 5;
    const int lane = tid & 31;
    const int n0   = blockIdx.x * 128;
    const int m0   = blockIdx.y * 64;
    const int S    = 2 * (DI / 32);   // 96 (dir0 then dir1)

    const __nv_bfloat16* lsrc[6];
    size_t diroff[6];
    uint32_t ldst[6];
#pragma unroll
    for (int j = 0; j < 6; ++j) {
        const int id  = tid + j * 256;
        const int ck  = id & 3;
        const int row = id >> 2;
        const __nv_bfloat16* base;
        uint32_t arrbase;
        size_t grow;
        if (row < 64)       { base = g_Ah1; arrbase = 0;                     grow = (size_t)(m0 + row);         diroff[j] = (size_t)M4 * DI; }
        else if (row < 128) { base = g_Al1; arrbase = ARR_A64;               grow = (size_t)(m0 + row - 64);    diroff[j] = (size_t)M4 * DI; }
        else if (row < 256) { base = g_Wh1; arrbase = 2 * ARR_A64;           grow = (size_t)(n0 + row - 128);   diroff[j] = (size_t)DM * DI; }
        else                { base = g_Wl1; arrbase = 2 * ARR_A64 + ARR_B1;  grow = (size_t)(n0 + row - 256);   diroff[j] = (size_t)DM * DI; }
        lsrc[j] = base + grow * DI + ck * 8;
        const int lrow = (row < 64) ? row : (row < 128) ? (row - 64)
                       : (row < 256) ? (row - 128) : (row - 256);
        ldst[j] = sb + arrbase + (uint32_t)lrow * 80 + ck * 16;
    }

#define ISSUE1(s) do {                                                       \
        const int _s = (s);                                                  \
        const int _d = (_s >= 48);                                           \
        const int _k0 = (_s - _d * 48) * 32;                                 \
        const uint32_t _so = (_s & 1) * STG1;                                \
        _Pragma("unroll")                                                    \
        for (int _j = 0; _j < 6; ++_j)                                       \
            cpa16(ldst[_j] + _so, lsrc[_j] + (_d ? diroff[_j] : 0) + _k0);   \
        asm volatile("cp.async.commit_group;" ::: "memory");                 \
    } while (0)

    float acc[2][4][4];
#pragma unroll
    for (int i = 0; i < 2; ++i)
#pragma unroll
        for (int j = 0; j < 4; ++j)
#pragma unroll
            for (int k = 0; k < 4; ++k) acc[i][j][k] = 0.f;

    const int wm  = (wid >> 2) * 32;
    const int wn  = (wid & 3) * 32;
    const int arl = (lane & 7) + ((lane >> 3) & 1) * 8;
    const int akb = (lane >> 4) * 16;
    const int brl = (lane & 7) + (lane >> 4) * 8;
    const int bkb = ((lane >> 3) & 1) * 16;

    ISSUE1(0);
    ISSUE1(1);

    for (int s = 0; s < S; ++s) {
        if (s == S - 1) asm volatile("cp.async.wait_group 0;" ::: "memory");
        else            asm volatile("cp.async.wait_group 1;" ::: "memory");
        __syncthreads();

        const uint32_t ub  = sb + (s & 1) * STG1;
        const uint32_t uAh = ub;
        const uint32_t uAl = ub + ARR_A64;
        const uint32_t uBh = ub + 2 * ARR_A64;
        const uint32_t uBl = ub + 2 * ARR_A64 + ARR_B1;

#pragma unroll
        for (int ks = 0; ks < 2; ++ks) {
            uint32_t ah[2][4], al_[2][4], bh[2][4], bl[2][4];
#pragma unroll
            for (int mf = 0; mf < 2; ++mf) {
                const uint32_t off = (uint32_t)(wm + mf * 16 + arl) * 80 + ks * 32 + akb;
                ldsm4(ah[mf][0],  ah[mf][1],  ah[mf][2],  ah[mf][3],  uAh + off);
                ldsm4(al_[mf][0], al_[mf][1], al_[mf][2], al_[mf][3], uAl + off);
            }
#pragma unroll
            for (int nf2 = 0; nf2 < 2; ++nf2) {
                const uint32_t off = (uint32_t)(wn + nf2 * 16 + brl) * 80 + ks * 32 + bkb;
                ldsm4(bh[nf2][0], bh[nf2][1], bh[nf2][2], bh[nf2][3], uBh + off);
                ldsm4(bl[nf2][0], bl[nf2][1], bl[nf2][2], bl[nf2][3], uBl + off);
            }
#pragma unroll
            for (int mf = 0; mf < 2; ++mf)
#pragma unroll
                for (int nf2 = 0; nf2 < 2; ++nf2)
#pragma unroll
                    for (int hf = 0; hf < 2; ++hf) {
                        float* c = acc[mf][nf2 * 2 + hf];
                        mma16816(c, ah[mf],  &bh[nf2][hf * 2]);
                        mma16816(c, ah[mf],  &bl[nf2][hf * 2]);
                        mma16816(c, al_[mf], &bh[nf2][hf * 2]);
                    }
        }
        __syncthreads();
        if (s + 2 < S) ISSUE1(s + 2);
    }
#undef ISSUE1

    const int g  = lane >> 2;
    const int tg = lane & 3;
#pragma unroll
    for (int mf = 0; mf < 2; ++mf)
#pragma unroll
        for (int nf = 0; nf < 4; ++nf) {
            const int mrow = m0 + wm + mf * 16 + g;
            const int ncol = n0 + wn + nf * 8 + tg * 2;
            const float* c = acc[mf][nf];
            float* o0 = Cg + (size_t)mrow * DM + ncol;
            float* o1 = Cg + (size_t)(mrow + 8) * DM + ncol;
            o0[0] = c[0]; o0[1] = c[1];
            o1[0] = c[2]; o1[1] = c[3];
        }
}

// =====================================================================
// dt/dA precompute (both dirs)
// =====================================================================
__global__ void dtdA_kernel(const float* __restrict__ dt_bias,
                            const float* __restrict__ A_log)
{
    const int idx = blockIdx.x * 256 + threadIdx.x;
    if (idx >= 2 * M4 * NH) return;
    const int hh  = idx % NH;
    const int rm  = idx / NH;
    const int dir = rm >> 12;
    const float raw = g_zx[(size_t)rm * NPROJ + (DI + CONVD) + hh] + dt_bias[dir * NH + hh];
    const float dtv = (raw > 20.f) ? raw : log1pf(__expf(raw));
    const float A   = -__expf(A_log[dir * NH + hh]);
    g_dt[idx] = dtv;
    g_dA[idx] = __expf(dtv * A);
}

// =====================================================================
// depthwise causal conv(4) + SiLU (both dirs; grid z = dir*2+b)
// =====================================================================
__global__ void __launch_bounds__(256) conv_kernel(const float* __restrict__ conv_w,
                                                   const float* __restrict__ conv_b)
{
    const int db  = blockIdx.z;
    const int dir = db >> 1;
    const int b   = db & 1;
    const int t0  = blockIdx.y * 32;
    const int tid = threadIdx.x;
    const int c   = blockIdx.x * 256 + tid;

    __shared__ float s[35][256];

#pragma unroll
    for (int rr = 0; rr < 35; ++rr) {
        const int tin = t0 - 3 + rr;
        float val = 0.f;
        if (tin >= 0)
            val = g_zx[((size_t)(dir * M4 + b * L + tin)) * NPROJ + DI + c];
        s[rr][tid] = val;
    }
    __syncthreads();
    const float w0 = conv_w[(dir * CONVD + c) * 4 + 0];
    const float w1 = conv_w[(dir * CONVD + c) * 4 + 1];
    const float w2 = conv_w[(dir * CONVD + c) * 4 + 2];
    const float w3 = conv_w[(dir * CONVD + c) * 4 + 3];
    const float bias = conv_b[dir * CONVD + c];
#pragma unroll 4
    for (int tt = 0; tt < 32; ++tt) {
        float v = bias;
        v = fmaf(s[tt + 0][tid], w0, v);
        v = fmaf(s[tt + 1][tid], w1, v);
        v = fmaf(s[tt + 2][tid], w2, v);
        v = fmaf(s[tt + 3][tid], w3, v);
        g_xBC[((size_t)(dir * M4 + b * L + t0 + tt)) * CONVD + c] = fast_silu(v);
    }
}

// =====================================================================
// scan pass A (both dirs): grid (NH, NCH, 4)
// =====================================================================
__global__ void __launch_bounds__(128) scanA(const float* __restrict__ Dvec)
{
    const int h     = blockIdx.x;
    const int chunk = blockIdx.y;
    const int dirb  = blockIdx.z;
    const int dir   = dirb >> 1;
    const int b     = dirb & 1;
    const int tid   = threadIdx.x;
    const int ni    = tid & 7;
    const int pi    = tid >> 3;

    __shared__ float sx[3][64];
    __shared__ float sB[3][128];
    __shared__ float sC[3][128];
    __shared__ float ss[3][2];

    const float Dval  = Dvec[dir * NH + h];
    const int rowbase = dir * M4 + b * L;
    const int t0      = chunk * CS;

    u64t hreg[4][8];
#pragma unroll
    for (int pp = 0; pp < 4; ++pp)
#pragma unroll
        for (int nn = 0; nn < 8; ++nn) hreg[pp][nn] = 0ull;

    {
        const float* row = g_xBC + (size_t)(rowbase + t0) * CONVD;
        if (tid < 64) sx[0][tid] = row[h * HD + tid];
        sB[0][tid] = row[DI + tid];
        sC[0][tid] = row[DI + DS + tid];
        if (tid == 0) {
            ss[0][0] = g_dt[(size_t)(rowbase + t0) * NH + h];
            ss[0][1] = g_dA[(size_t)(rowbase + t0) * NH + h];
        }
    }
    __syncthreads();

    float cp = 1.f;
    int cur = 0;
    for (int tt = 0; tt < CS; ++tt) {
        const int t = t0 + tt;
        float rx = 0.f, rb = 0.f, rc = 0.f, rdt = 0.f, rdA = 0.f;
        if (tt + 1 < CS) {
            const float* row = g_xBC + (size_t)(rowbase + t + 1) * CONVD;
            if (tid < 64) rx = row[h * HD + tid];
            rb = row[DI + tid];
            rc = row[DI + DS + tid];
            if (tid == 0) {
                rdt = g_dt[(size_t)(rowbase + t + 1) * NH + h];
                rdA = g_dA[(size_t)(rowbase + t + 1) * NH + h];
            }
        }

        const float dt = ss[cur][0];
        const float dA = ss[cur][1];
        const u64t dA2 = pack2(dA, dA);
        float xv[4];
        u64t coef2[4], acc2[4];
#pragma unroll
        for (int pp = 0; pp < 4; ++pp) {
            xv[pp] = sx[cur][pi * 4 + pp];
            const float cf = dt * xv[pp];
            coef2[pp] = pack2(cf, cf);
            acc2[pp]  = 0ull;
        }
#pragma unroll
        for (int nn = 0; nn < 8; ++nn) {
            const float2 bv = *(const float2*)&sB[cur][ni * 16 + nn * 2];
            const float2 cv = *(const float2*)&sC[cur][ni * 16 + nn * 2];
            const u64t B2 = pack2(bv.x, bv.y);
            const u64t C2 = pack2(cv.x, cv.y);
#pragma unroll
            for (int pp = 0; pp < 4; ++pp) {
                const u64t tmb = mul2(coef2[pp], B2);
                const u64t hv  = fma2(hreg[pp][nn], dA2, tmb);
                hreg[pp][nn] = hv;
                acc2[pp] = fma2(hv, C2, acc2[pp]);
            }
        }
        float acc[4];
#pragma unroll
        for (int pp = 0; pp < 4; ++pp) {
            float lo, hi; unpack2(acc2[pp], lo, hi);
            acc[pp] = lo + hi;
            acc[pp] += __shfl_xor_sync(0xffffffffu, acc[pp], 1);
            acc[pp] += __shfl_xor_sync(0xffffffffu, acc[pp], 2);
            acc[pp] += __shfl_xor_sync(0xffffffffu, acc[pp], 4);
        }
        cp *= dA;
        if (ni == 0) {
            float* yp = g_y + (size_t)(rowbase + t) * DI + h * HD + pi * 4;
#pragma unroll
            for (int pp = 0; pp < 4; ++pp)
                yp[pp] = fmaf(Dval, xv[pp], acc[pp]);
        }
        if (tid == 0)
            g_cumP[(size_t)(rowbase + t) * NH + h] = cp;

        const int nxt = (cur == 2) ? 0 : cur + 1;
        if (tt + 1 < CS) {
            if (tid < 64) sx[nxt][tid] = rx;
            sB[nxt][tid] = rb;
            sC[nxt][tid] = rc;
            if (tid == 0) { ss[nxt][0] = rdt; ss[nxt][1] = rdA; }
        }
        __syncthreads();
        cur = nxt;
    }

    const size_t base = ((size_t)(dirb * NH + h) * NCH + chunk) * (HD * DS) + (size_t)tid * 64;
#pragma unroll
    for (int pp = 0; pp < 4; ++pp)
#pragma unroll
        for (int nn = 0; nn < 8; ++nn)
            *(u64t*)&g_lend[base + pp * 16 + nn * 2] = hreg[pp][nn];
}

// =====================================================================
// scan pass B (both dirs): 96 blocks, register-resident chains
// =====================================================================
__global__ void __launch_bounds__(256) scanB()
{
    const int gid  = blockIdx.x;             // dirb*NH + h
    const int dirb = gid / NH;
    const int h    = gid % NH;
    const int rowbase = (dirb >> 1) * M4 + (dirb & 1) * L;
    const int tid  = threadIdx.x;

    __shared__ float pe[NCH];
    if (tid < NCH)
        pe[tid] = g_cumP[(size_t)(rowbase + tid * CS + CS - 1) * NH + h];
    __syncthreads();

    const size_t gbase = (size_t)gid * NCH * (HD * DS);
    float4 H[8];
#pragma unroll
    for (int j = 0; j < 8; ++j) H[j] = make_float4(0.f, 0.f, 0.f, 0.f);

    for (int c = 0; c < NCH; ++c) {
        const float p = pe[c];
        const size_t cb = gbase + (size_t)c * (HD * DS) + tid * 4;
        float4 v[8];
#pragma unroll
        for (int j = 0; j < 8; ++j)
            v[j] = *(const float4*)&g_lend[cb + j * 1024];
#pragma unroll
        for (int j = 0; j < 8; ++j) {
            *(float4*)&g_hcarry[cb + j * 1024] = H[j];
            H[j].x = fmaf(p, H[j].x, v[j].x);
            H[j].y = fmaf(p, H[j].y, v[j].y);
            H[j].z = fmaf(p, H[j].z, v[j].z);
            H[j].w = fmaf(p, H[j].w, v[j].w);
        }
    }
}

// =====================================================================
// scan pass C (both dirs): grid (NH, NCH-1, 4)
// =====================================================================
__global__ void __launch_bounds__(128) scanC()
{
    const int h     = blockIdx.x;
    const int chunk = blockIdx.y + 1;
    const int dirb  = blockIdx.z;
    const int tid   = threadIdx.x;
    const int ni    = tid & 7;
    const int pi    = tid >> 3;

    const int rowbase = (dirb >> 1) * M4 + (dirb & 1) * L;
    const int t0      = chunk * CS;

    u64t hc[4][8];
    {
        const size_t base = ((size_t)(dirb * NH + h) * NCH + chunk) * (HD * DS) + (size_t)tid * 64;
#pragma unroll
        for (int pp = 0; pp < 4; ++pp)
#pragma unroll
            for (int nn = 0; nn < 8; ++nn)
                hc[pp][nn] = *(const u64t*)&g_hcarry[base + pp * 16 + nn * 2];
    }

    for (int tt = 0; tt < CS; ++tt) {
        const int t = t0 + tt;
        const float* crow = g_xBC + (size_t)(rowbase + t) * CONVD + DI + DS + ni * 16;
        const float4 c0 = *(const float4*)(crow);
        const float4 c1 = *(const float4*)(crow + 4);
        const float4 c2 = *(const float4*)(crow + 8);
        const float4 c3 = *(const float4*)(crow + 12);
        u64t C2[8];
        C2[0] = pack2(c0.x, c0.y); C2[1] = pack2(c0.z, c0.w);
        C2[2] = pack2(c1.x, c1.y); C2[3] = pack2(c1.z, c1.w);
        C2[4] = pack2(c2.x, c2.y); C2[5] = pack2(c2.z, c2.w);
        C2[6] = pack2(c3.x, c3.y); C2[7] = pack2(c3.z, c3.w);
        u64t acc2[4] = {0ull, 0ull, 0ull, 0ull};
#pragma unroll
        for (int nn = 0; nn < 8; ++nn)
#pragma unroll
            for (int pp = 0; pp < 4; ++pp)
                acc2[pp] = fma2(hc[pp][nn], C2[nn], acc2[pp]);
        float acc[4];
#pragma unroll
        for (int pp = 0; pp < 4; ++pp) {
            float lo, hi; unpack2(acc2[pp], lo, hi);
            acc[pp] = lo + hi;
            acc[pp] += __shfl_xor_sync(0xffffffffu, acc[pp], 1);
            acc[pp] += __shfl_xor_sync(0xffffffffu, acc[pp], 2);
            acc[pp] += __shfl_xor_sync(0xffffffffu, acc[pp], 4);
        }
        if (ni == 0) {
            const float cumP = g_cumP[(size_t)(rowbase + t) * NH + h];
            float* yp = g_y + (size_t)(rowbase + t) * DI + h * HD + pi * 4;
#pragma unroll
            for (int pp = 0; pp < 4; ++pp)
                yp[pp] = fmaf(cumP, acc[pp], yp[pp]);
        }
    }
}

// =====================================================================
// gate + RMSNorm (both dirs); emits split bf16 A-operand (dir-flipped)
// =====================================================================
__global__ void __launch_bounds__(256) gatenorm_kernel(const float* __restrict__ norm_w)
{
    const int row = blockIdx.x;              // dir*M4 + m
    const int dir = row >> 12;
    const int m   = row & (M4 - 1);
    const int tid = threadIdx.x;
    const float* yrow = g_y + (size_t)row * DI;
    const float* zrow = g_zx + (size_t)row * NPROJ;

    float v[6];
    float ssum = 0.f;
#pragma unroll
    for (int i = 0; i < 6; ++i) {
        const int c = tid + i * 256;
        const float val = yrow[c] * fast_silu(zrow[c]);
        v[i] = val;
        ssum += val * val;
    }
#pragma unroll
    for (int o = 16; o > 0; o >>= 1)
        ssum += __shfl_xor_sync(0xffffffffu, ssum, o);

    __shared__ float red[8];
    if ((tid & 31) == 0) red[tid >> 5] = ssum;
    __syncthreads();
    if (tid == 0) {
        float tot = 0.f;
#pragma unroll
        for (int i = 0; i < 8; ++i) tot += red[i];
        red[0] = rsqrtf(tot / (float)DI + 1e-5f);
    }
    __syncthreads();
    const float scale = red[0];

    const int t    = m & (L - 1);
    const int dstm = dir ? (m - t + (L - 1 - t)) : m;
    __nv_bfloat16* ah = g_Ah1 + ((size_t)dir * M4 + dstm) * DI;
    __nv_bfloat16* al = g_Al1 + ((size_t)dir * M4 + dstm) * DI;

#pragma unroll
    for (int i = 0; i < 6; ++i) {
        const int c = tid + i * 256;
        const float val = v[i] * scale * norm_w[dir * DI + c];
        const __nv_bfloat16 hb = __float2bfloat16(val);
        const float lf = val - __bfloat162float(hb);
        ah[c] = hb;
        al[c] = __float2bfloat16(lf);
    }
}

// =====================================================================
// launch — straight-line, full-width schedule (single stream)
// =====================================================================
extern "C" void kernel_launch(void* const* d_in, const int* in_sizes, int n_in,
                              void* d_out, int out_size)
{
    (void)in_sizes; (void)n_in; (void)out_size;
    const float* x       = (const float*)d_in[0];
    const float* in_w    = (const float*)d_in[1];
    const float* conv_w  = (const float*)d_in[2];
    const float* conv_b  = (const float*)d_in[3];
    const float* dt_bias = (const float*)d_in[4];
    const float* A_log   = (const float*)d_in[5];
    const float* Dp      = (const float*)d_in[6];
    const float* norm_w  = (const float*)d_in[7];
    const float* out_w   = (const float*)d_in[8];
    float* out = (float*)d_out;

    cudaFuncSetAttribute((const void*)gemm0,
                         cudaFuncAttributeMaxDynamicSharedMemorySize, GSMEM);
    cudaFuncSetAttribute((const void*)gemm1,
                         cudaFuncAttributeMaxDynamicSharedMemorySize, SMEM1);

    split_x <<<(M4 * (DM / 4) + 255) / 256, 256>>>(x);
    split_w0<<<(2 * NPAD * (DM / 4) + 255) / 256, 256>>>(in_w);
    split_w1<<<(2 * DM * (DI / 4) + 255) / 256, 256>>>(out_w);

    gemm0<<<dim3(NPAD / 128, M4 / 128, 2), 256, GSMEM>>>();

    conv_kernel<<<dim3(CONVD / 256, L / 32, 4), 256>>>(conv_w, conv_b);
    dtdA_kernel<<<(2 * M4 * NH + 255) / 256, 256>>>(dt_bias, A_log);

    scanA<<<dim3(NH, NCH, 4), 128>>>(Dp);
    scanB<<<96, 256>>>();
    scanC<<<dim3(NH, NCH - 1, 4), 128>>>();

    gatenorm_kernel<<<2 * M4, 256>>>(norm_w);
    gemm1<<<dim3(DM / 128, M4 / 64), 256, SMEM1>>>(out);
}

// round 17
// speedup vs baseline: 1.0191x; 1.0191x over previous
#include <cuda_runtime.h>
#include <cuda_bf16.h>
#include <math.h>
#include <cstdint>
#include <cstring>

// ---------------- problem constants ----------------
#define L       2048
#define BATCH   2
#define DM      768
#define DI      1536
#define DS      128
#define HD      64
#define NH      24
#define CONVD   1792
#define NPROJ   3352
#define NPAD    3456          // 27 * 128
#define M4      4096
#define CS      128
#define NCH     (L / CS)      // 16

// ---------------- scratch ----------------
__device__ float g_zx [2u * M4 * NPROJ];
__device__ float g_xBC[2u * M4 * CONVD];
__device__ float g_dt [2u * M4 * NH];
__device__ float g_dA [2u * M4 * NH];
__device__ float g_y  [2u * M4 * DI];
__device__ float g_cumP[2u * M4 * NH];
__device__ float g_lend  [96u * NCH * (HD * DS)];
__device__ float g_hcarry[96u * NCH * (HD * DS)];

__device__ __nv_bfloat16 g_Ah0[(size_t)M4 * DM],   g_Al0[(size_t)M4 * DM];   // linear (dir0 order)
__device__ __nv_bfloat16 g_Wh0[2u * NPAD * DM], g_Wl0[2u * NPAD * DM];
__device__ __nv_bfloat16 g_Ah1[2u * M4 * DI],   g_Al1[2u * M4 * DI];
__device__ __nv_bfloat16 g_Wh1[2u * DM * DI],   g_Wl1[2u * DM * DI];

// =====================================================================
// helpers
// =====================================================================
__device__ __forceinline__ uint32_t smem_u32(const void* p) {
    uint32_t a;
    asm("{ .reg .u64 t; cvta.to.shared.u64 t, %1; cvt.u32.u64 %0, t; }" : "=r"(a) : "l"(p));
    return a;
}
__device__ __forceinline__ uint32_t b2u(__nv_bfloat162 v) {
    uint32_t u; memcpy(&u, &v, 4); return u;
}
__device__ __forceinline__ void ldsm4(uint32_t& r0, uint32_t& r1, uint32_t& r2, uint32_t& r3,
                                      uint32_t addr) {
    asm volatile("ldmatrix.sync.aligned.m8n8.x4.shared.b16 {%0,%1,%2,%3}, [%4];"
        : "=r"(r0), "=r"(r1), "=r"(r2), "=r"(r3) : "r"(addr));
}
__device__ __forceinline__ void mma16816(float* c, const uint32_t* a, const uint32_t* b) {
    asm volatile(
        "mma.sync.aligned.m16n8k16.row.col.f32.bf16.bf16.f32 "
        "{%0,%1,%2,%3}, {%4,%5,%6,%7}, {%8,%9}, {%0,%1,%2,%3};"
        : "+f"(c[0]), "+f"(c[1]), "+f"(c[2]), "+f"(c[3])
        : "r"(a[0]), "r"(a[1]), "r"(a[2]), "r"(a[3]), "r"(b[0]), "r"(b[1]));
}
__device__ __forceinline__ void cpa16(uint32_t dst, const void* src) {
    asm volatile("cp.async.cg.shared.global [%0], [%1], 16;" :: "r"(dst), "l"(src));
}
__device__ __forceinline__ void split4(float4 v, uint2& h, uint2& l) {
    __nv_bfloat162 h0 = __float22bfloat162_rn(make_float2(v.x, v.y));
    __nv_bfloat162 h1 = __float22bfloat162_rn(make_float2(v.z, v.w));
    float2 f0 = __bfloat1622float2(h0), f1 = __bfloat1622float2(h1);
    __nv_bfloat162 l0 = __float22bfloat162_rn(make_float2(v.x - f0.x, v.y - f0.y));
    __nv_bfloat162 l1 = __float22bfloat162_rn(make_float2(v.z - f1.x, v.w - f1.y));
    h = make_uint2(b2u(h0), b2u(h1));
    l = make_uint2(b2u(l0), b2u(l1));
}
typedef unsigned long long u64t;
__device__ __forceinline__ u64t pack2(float a, float b) {
    u64t r; asm("mov.b64 %0, {%1, %2};" : "=l"(r) : "f"(a), "f"(b)); return r;
}
__device__ __forceinline__ void unpack2(u64t v, float& a, float& b) {
    asm("mov.b64 {%0, %1}, %2;" : "=f"(a), "=f"(b) : "l"(v));
}
__device__ __forceinline__ u64t fma2(u64t a, u64t b, u64t c) {
    u64t d; asm("fma.rn.f32x2 %0, %1, %2, %3;" : "=l"(d) : "l"(a), "l"(b), "l"(c)); return d;
}
__device__ __forceinline__ u64t mul2(u64t a, u64t b) {
    u64t d; asm("mul.rn.f32x2 %0, %1, %2;" : "=l"(d) : "l"(a), "l"(b)); return d;
}
__device__ __forceinline__ float fast_silu(float v) {
    return __fdividef(v, 1.f + __expf(-v));
}

// =====================================================================
// operand split kernels
// =====================================================================
__global__ void __launch_bounds__(256) split_x(const float* __restrict__ x)
{
    const int idx = blockIdx.x * 256 + threadIdx.x;   // over M4*(DM/4), linear
    if (idx >= M4 * (DM / 4)) return;
    const float4 v = *(const float4*)(x + (size_t)idx * 4);
    uint2 h, l; split4(v, h, l);
    *(uint2*)(g_Ah0 + (size_t)idx * 4) = h;
    *(uint2*)(g_Al0 + (size_t)idx * 4) = l;
}

__global__ void __launch_bounds__(256) split_w0(const float* __restrict__ w)
{
    const int idx = blockIdx.x * 256 + threadIdx.x;
    if (idx >= 2 * NPAD * (DM / 4)) return;
    const int k4 = idx % (DM / 4);
    const int rn = idx / (DM / 4);
    const int n  = rn % NPAD;
    const int dir = rn / NPAD;
    float4 v = make_float4(0.f, 0.f, 0.f, 0.f);
    if (n < NPROJ)
        v = *(const float4*)(w + ((size_t)dir * NPROJ + n) * DM + k4 * 4);
    uint2 h, l; split4(v, h, l);
    *(uint2*)(g_Wh0 + (size_t)rn * DM + k4 * 4) = h;
    *(uint2*)(g_Wl0 + (size_t)rn * DM + k4 * 4) = l;
}

__global__ void __launch_bounds__(256) split_w1(const float* __restrict__ w)
{
    const int idx = blockIdx.x * 256 + threadIdx.x;
    if (idx >= 2 * DM * (DI / 4)) return;
    const float4 v = *(const float4*)(w + (size_t)idx * 4);
    uint2 h, l; split4(v, h, l);
    *(uint2*)(g_Wh1 + (size_t)idx * 4) = h;
    *(uint2*)(g_Wl1 + (size_t)idx * 4) = l;
}

// =====================================================================
// in_proj GEMM (per dir); BM=BN=128, 2-stage, 2 CTAs/SM.
// dir1 reads the linear A-split arrays with per-row flipped indexing.
// =====================================================================
#define GARR  10240
#define GSTG  (4 * GARR)
#define GSMEM (2 * GSTG)

__global__ void __launch_bounds__(256, 2) gemm0(int dir0)
{
    extern __shared__ __align__(128) char smem[];
    const uint32_t sb = smem_u32(smem);

    const int tid  = threadIdx.x;
    const int wid  = tid >> 5;
    const int lane = tid & 31;
    const int n0   = blockIdx.x * 128;
    const int m0   = blockIdx.y * 128;
    const int S    = DM / 32;

    const int arr = tid >> 6;
    const int rw0 = (tid & 63) * 2;
    const uint32_t sdst0 = sb + arr * GARR + rw0 * 80;

    const __nv_bfloat16* srcp;
    int rstr;
    if (arr < 2) {
        const __nv_bfloat16* base = arr ? g_Al0 : g_Ah0;
        const int m = m0 + rw0;
        if (dir0 == 0) {
            srcp = base + (size_t)m * DM;
            rstr = DM;
        } else {
            const int t  = m & (L - 1);
            const int sm = (m - t) + (L - 1 - t);
            srcp = base + (size_t)sm * DM;
            rstr = -DM;
        }
    } else {
        const __nv_bfloat16* base = (arr == 2) ? g_Wh0 : g_Wl0;
        srcp = base + ((size_t)dir0 * NPAD + n0 + rw0) * DM;
        rstr = DM;
    }

#define ISSUE0(s) do {                                                       \
        const int _s = (s);                                                  \
        const __nv_bfloat16* _p = srcp + _s * 32;                            \
        const uint32_t _dst = sdst0 + (_s & 1) * GSTG;                       \
        cpa16(_dst +  0, _p);                                                \
        cpa16(_dst + 16, _p + 8);                                            \
        cpa16(_dst + 32, _p + 16);                                           \
        cpa16(_dst + 48, _p + 24);                                           \
        cpa16(_dst + 80 +  0, _p + rstr);                                    \
        cpa16(_dst + 80 + 16, _p + rstr + 8);                                \
        cpa16(_dst + 80 + 32, _p + rstr + 16);                               \
        cpa16(_dst + 80 + 48, _p + rstr + 24);                               \
        asm volatile("cp.async.commit_group;" ::: "memory");                 \
    } while (0)

    float acc[4][4][4];
#pragma unroll
    for (int i = 0; i < 4; ++i)
#pragma unroll
        for (int j = 0; j < 4; ++j)
#pragma unroll
            for (int k = 0; k < 4; ++k) acc[i][j][k] = 0.f;

    const int wm  = (wid >> 2) * 64;
    const int wn  = (wid & 3) * 32;
    const int arl = (lane & 7) + ((lane >> 3) & 1) * 8;
    const int akb = (lane >> 4) * 16;
    const int brl = (lane & 7) + (lane >> 4) * 8;
    const int bkb = ((lane >> 3) & 1) * 16;

    ISSUE0(0);
    ISSUE0(1);

    for (int s = 0; s < S; ++s) {
        if (s == S - 1) asm volatile("cp.async.wait_group 0;" ::: "memory");
        else            asm volatile("cp.async.wait_group 1;" ::: "memory");
        __syncthreads();

        const uint32_t ub  = sb + (s & 1) * GSTG;
        const uint32_t uAh = ub;
        const uint32_t uAl = ub + GARR;
        const uint32_t uBh = ub + 2 * GARR;
        const uint32_t uBl = ub + 3 * GARR;

#pragma unroll
        for (int ks = 0; ks < 2; ++ks) {
            uint32_t ah[4][4], al_[4][4], bh[2][4], bl[2][4];
#pragma unroll
            for (int mf = 0; mf < 4; ++mf) {
                const uint32_t off = (uint32_t)(wm + mf * 16 + arl) * 80 + ks * 32 + akb;
                ldsm4(ah[mf][0],  ah[mf][1],  ah[mf][2],  ah[mf][3],  uAh + off);
                ldsm4(al_[mf][0], al_[mf][1], al_[mf][2], al_[mf][3], uAl + off);
            }
#pragma unroll
            for (int nf2 = 0; nf2 < 2; ++nf2) {
                const uint32_t off = (uint32_t)(wn + nf2 * 16 + brl) * 80 + ks * 32 + bkb;
                ldsm4(bh[nf2][0], bh[nf2][1], bh[nf2][2], bh[nf2][3], uBh + off);
                ldsm4(bl[nf2][0], bl[nf2][1], bl[nf2][2], bl[nf2][3], uBl + off);
            }
#pragma unroll
            for (int mf = 0; mf < 4; ++mf)
#pragma unroll
                for (int nf2 = 0; nf2 < 2; ++nf2)
#pragma unroll
                    for (int hf = 0; hf < 2; ++hf) {
                        float* c = acc[mf][nf2 * 2 + hf];
                        mma16816(c, ah[mf],  &bh[nf2][hf * 2]);
                        mma16816(c, ah[mf],  &bl[nf2][hf * 2]);
                        mma16816(c, al_[mf], &bh[nf2][hf * 2]);
                    }
        }
        __syncthreads();
        if (s + 2 < S) ISSUE0(s + 2);
    }
#undef ISSUE0

    const int g  = lane >> 2;
    const int tg = lane & 3;
#pragma unroll
    for (int mf = 0; mf < 4; ++mf)
#pragma unroll
        for (int nf = 0; nf < 4; ++nf) {
            const int mrow = m0 + wm + mf * 16 + g;
            const int ncol = n0 + wn + nf * 8 + tg * 2;
            const float* c = acc[mf][nf];
            if (ncol < NPROJ) {
                float* o0 = g_zx + ((size_t)(dir0 * M4 + mrow)) * NPROJ + ncol;
                float* o1 = g_zx + ((size_t)(dir0 * M4 + mrow + 8)) * NPROJ + ncol;
                o0[0] = c[0]; o0[1] = c[1];
                o1[0] = c[2]; o1[1] = c[3];
            }
        }
}

// =====================================================================
// out_proj GEMM (merged dirs): BM=64, BN=128, grid (6,64)=384 blocks,
// 3 CTAs/SM, K = 2 x DI accumulated in one pass; writes final output.
// =====================================================================
#define ARR_A64 5120
#define ARR_B1  10240
#define STG1    (2 * ARR_A64 + 2 * ARR_B1)
#define SMEM1   (2 * STG1)

__global__ void __launch_bounds__(256, 3) gemm1(float* __restrict__ Cg)
{
    extern __shared__ __align__(128) char smem[];
    const uint32_t sb = smem_u32(smem);

    const int tid  = threadIdx.x;
    const int wid  = tid >> 5;
    const int lane = tid & 31;
    const int n0   = blockIdx.x * 128;
    const int m0   = blockIdx.y * 64;
    const int S    = 2 * (DI / 32);   // 96

    const __nv_bfloat16* lsrc[6];
    size_t diroff[6];
    uint32_t ldst[6];
#pragma unroll
    for (int j = 0; j < 6; ++j) {
        const int id  = tid + j * 256;
        const int ck  = id & 3;
        const int row = id >> 2;
        const __nv_bfloat16* base;
        uint32_t arrbase;
        size_t grow;
        if (row < 64)       { base = g_Ah1; arrbase = 0;                     grow = (size_t)(m0 + row);         diroff[j] = (size_t)M4 * DI; }
        else if (row < 128) { base = g_Al1; arrbase = ARR_A64;               grow = (size_t)(m0 + row - 64);    diroff[j] = (size_t)M4 * DI; }
        else if (row < 256) { base = g_Wh1; arrbase = 2 * ARR_A64;           grow = (size_t)(n0 + row - 128);   diroff[j] = (size_t)DM * DI; }
        else                { base = g_Wl1; arrbase = 2 * ARR_A64 + ARR_B1;  grow = (size_t)(n0 + row - 256);   diroff[j] = (size_t)DM * DI; }
        lsrc[j] = base + grow * DI + ck * 8;
        const int lrow = (row < 64) ? row : (row < 128) ? (row - 64)
                       : (row < 256) ? (row - 128) : (row - 256);
        ldst[j] = sb + arrbase + (uint32_t)lrow * 80 + ck * 16;
    }

#define ISSUE1(s) do {                                                       \
        const int _s = (s);                                                  \
        const int _d = (_s >= 48);                                           \
        const int _k0 = (_s - _d * 48) * 32;                                 \
        const uint32_t _so = (_s & 1) * STG1;                                \
        _Pragma("unroll")                                                    \
        for (int _j = 0; _j < 6; ++_j)                                       \
            cpa16(ldst[_j] + _so, lsrc[_j] + (_d ? diroff[_j] : 0) + _k0);   \
        asm volatile("cp.async.commit_group;" ::: "memory");                 \
    } while (0)

    float acc[2][4][4];
#pragma unroll
    for (int i = 0; i < 2; ++i)
#pragma unroll
        for (int j = 0; j < 4; ++j)
#pragma unroll
            for (int k = 0; k < 4; ++k) acc[i][j][k] = 0.f;

    const int wm  = (wid >> 2) * 32;
    const int wn  = (wid & 3) * 32;
    const int arl = (lane & 7) + ((lane >> 3) & 1) * 8;
    const int akb = (lane >> 4) * 16;
    const int brl = (lane & 7) + (lane >> 4) * 8;
    const int bkb = ((lane >> 3) & 1) * 16;

    ISSUE1(0);
    ISSUE1(1);

    for (int s = 0; s < S; ++s) {
        if (s == S - 1) asm volatile("cp.async.wait_group 0;" ::: "memory");
        else            asm volatile("cp.async.wait_group 1;" ::: "memory");
        __syncthreads();

        const uint32_t ub  = sb + (s & 1) * STG1;
        const uint32_t uAh = ub;
        const uint32_t uAl = ub + ARR_A64;
        const uint32_t uBh = ub + 2 * ARR_A64;
        const uint32_t uBl = ub + 2 * ARR_A64 + ARR_B1;

#pragma unroll
        for (int ks = 0; ks < 2; ++ks) {
            uint32_t ah[2][4], al_[2][4], bh[2][4], bl[2][4];
#pragma unroll
            for (int mf = 0; mf < 2; ++mf) {
                const uint32_t off = (uint32_t)(wm + mf * 16 + arl) * 80 + ks * 32 + akb;
                ldsm4(ah[mf][0],  ah[mf][1],  ah[mf][2],  ah[mf][3],  uAh + off);
                ldsm4(al_[mf][0], al_[mf][1], al_[mf][2], al_[mf][3], uAl + off);
            }
#pragma unroll
            for (int nf2 = 0; nf2 < 2; ++nf2) {
                const uint32_t off = (uint32_t)(wn + nf2 * 16 + brl) * 80 + ks * 32 + bkb;
                ldsm4(bh[nf2][0], bh[nf2][1], bh[nf2][2], bh[nf2][3], uBh + off);
                ldsm4(bl[nf2][0], bl[nf2][1], bl[nf2][2], bl[nf2][3], uBl + off);
            }
#pragma unroll
            for (int mf = 0; mf < 2; ++mf)
#pragma unroll
                for (int nf2 = 0; nf2 < 2; ++nf2)
#pragma unroll
                    for (int hf = 0; hf < 2; ++hf) {
                        float* c = acc[mf][nf2 * 2 + hf];
                        mma16816(c, ah[mf],  &bh[nf2][hf * 2]);
                        mma16816(c, ah[mf],  &bl[nf2][hf * 2]);
                        mma16816(c, al_[mf], &bh[nf2][hf * 2]);
                    }
        }
        __syncthreads();
        if (s + 2 < S) ISSUE1(s + 2);
    }
#undef ISSUE1

    const int g  = lane >> 2;
    const int tg = lane & 3;
#pragma unroll
    for (int mf = 0; mf < 2; ++mf)
#pragma unroll
        for (int nf = 0; nf < 4; ++nf) {
            const int mrow = m0 + wm + mf * 16 + g;
            const int ncol = n0 + wn + nf * 8 + tg * 2;
            const float* c = acc[mf][nf];
            float* o0 = Cg + (size_t)mrow * DM + ncol;
            float* o1 = Cg + (size_t)(mrow + 8) * DM + ncol;
            o0[0] = c[0]; o0[1] = c[1];
            o1[0] = c[2]; o1[1] = c[3];
        }
}

// =====================================================================
// dt/dA precompute (per dir)
// =====================================================================
__global__ void dtdA_kernel(int dir, const float* __restrict__ dt_bias,
                            const float* __restrict__ A_log)
{
    const int idx = blockIdx.x * 256 + threadIdx.x;
    if (idx >= M4 * NH) return;
    const int hh = idx % NH;
    const int m  = idx / NH;
    const int rm = dir * M4 + m;
    const float raw = g_zx[(size_t)rm * NPROJ + (DI + CONVD) + hh] + dt_bias[dir * NH + hh];
    const float dtv = (raw > 20.f) ? raw : log1pf(__expf(raw));
    const float A   = -__expf(A_log[dir * NH + hh]);
    g_dt[rm * NH + hh] = dtv;
    g_dA[rm * NH + hh] = __expf(dtv * A);
}

// =====================================================================
// depthwise causal conv(4) + SiLU (per dir)
// =====================================================================
__global__ void __launch_bounds__(256) conv_kernel(int dir,
                                                   const float* __restrict__ conv_w,
                                                   const float* __restrict__ conv_b)
{
    const int b   = blockIdx.z;
    const int t0  = blockIdx.y * 32;
    const int tid = threadIdx.x;
    const int c   = blockIdx.x * 256 + tid;

    __shared__ float s[35][256];

#pragma unroll
    for (int rr = 0; rr < 35; ++rr) {
        const int tin = t0 - 3 + rr;
        float val = 0.f;
        if (tin >= 0)
            val = g_zx[((size_t)(dir * M4 + b * L + tin)) * NPROJ + DI + c];
        s[rr][tid] = val;
    }
    __syncthreads();
    const float w0 = conv_w[(dir * CONVD + c) * 4 + 0];
    const float w1 = conv_w[(dir * CONVD + c) * 4 + 1];
    const float w2 = conv_w[(dir * CONVD + c) * 4 + 2];
    const float w3 = conv_w[(dir * CONVD + c) * 4 + 3];
    const float bias = conv_b[dir * CONVD + c];
#pragma unroll 4
    for (int tt = 0; tt < 32; ++tt) {
        float v = bias;
        v = fmaf(s[tt + 0][tid], w0, v);
        v = fmaf(s[tt + 1][tid], w1, v);
        v = fmaf(s[tt + 2][tid], w2, v);
        v = fmaf(s[tt + 3][tid], w3, v);
        g_xBC[((size_t)(dir * M4 + b * L + t0 + tt)) * CONVD + c] = fast_silu(v);
    }
}

// =====================================================================
// scan pass A (per dir): CS=128 chunks, grid (NH, 16, 2)
// =====================================================================
__global__ void __launch_bounds__(128) scanA(int dir, const float* __restrict__ Dvec)
{
    const int h     = blockIdx.x;
    const int chunk = blockIdx.y;
    const int b     = blockIdx.z;
    const int dirb  = dir * 2 + b;
    const int tid   = threadIdx.x;
    const int ni    = tid & 7;
    const int pi    = tid >> 3;

    __shared__ float sx[3][64];
    __shared__ float sB[3][128];
    __shared__ float sC[3][128];
    __shared__ float ss[3][2];

    const float Dval  = Dvec[dir * NH + h];
    const int rowbase = dir * M4 + b * L;
    const int t0      = chunk * CS;

    u64t hreg[4][8];
#pragma unroll
    for (int pp = 0; pp < 4; ++pp)
#pragma unroll
        for (int nn = 0; nn < 8; ++nn) hreg[pp][nn] = 0ull;

    {
        const float* row = g_xBC + (size_t)(rowbase + t0) * CONVD;
        if (tid < 64) sx[0][tid] = row[h * HD + tid];
        sB[0][tid] = row[DI + tid];
        sC[0][tid] = row[DI + DS + tid];
        if (tid == 0) {
            ss[0][0] = g_dt[(size_t)(rowbase + t0) * NH + h];
            ss[0][1] = g_dA[(size_t)(rowbase + t0) * NH + h];
        }
    }
    __syncthreads();

    float cp = 1.f;
    int cur = 0;
    for (int tt = 0; tt < CS; ++tt) {
        const int t = t0 + tt;
        float rx = 0.f, rb = 0.f, rc = 0.f, rdt = 0.f, rdA = 0.f;
        if (tt + 1 < CS) {
            const float* row = g_xBC + (size_t)(rowbase + t + 1) * CONVD;
            if (tid < 64) rx = row[h * HD + tid];
            rb = row[DI + tid];
            rc = row[DI + DS + tid];
            if (tid == 0) {
                rdt = g_dt[(size_t)(rowbase + t + 1) * NH + h];
                rdA = g_dA[(size_t)(rowbase + t + 1) * NH + h];
            }
        }

        const float dt = ss[cur][0];
        const float dA = ss[cur][1];
        const u64t dA2 = pack2(dA, dA);
        float xv[4];
        u64t coef2[4], acc2[4];
#pragma unroll
        for (int pp = 0; pp < 4; ++pp) {
            xv[pp] = sx[cur][pi * 4 + pp];
            const float cf = dt * xv[pp];
            coef2[pp] = pack2(cf, cf);
            acc2[pp]  = 0ull;
        }
#pragma unroll
        for (int nn = 0; nn < 8; ++nn) {
            const float2 bv = *(const float2*)&sB[cur][ni * 16 + nn * 2];
            const float2 cv = *(const float2*)&sC[cur][ni * 16 + nn * 2];
            const u64t B2 = pack2(bv.x, bv.y);
            const u64t C2 = pack2(cv.x, cv.y);
#pragma unroll
            for (int pp = 0; pp < 4; ++pp) {
                const u64t tmb = mul2(coef2[pp], B2);
                const u64t hv  = fma2(hreg[pp][nn], dA2, tmb);
                hreg[pp][nn] = hv;
                acc2[pp] = fma2(hv, C2, acc2[pp]);
            }
        }
        float acc[4];
#pragma unroll
        for (int pp = 0; pp < 4; ++pp) {
            float lo, hi; unpack2(acc2[pp], lo, hi);
            acc[pp] = lo + hi;
            acc[pp] += __shfl_xor_sync(0xffffffffu, acc[pp], 1);
            acc[pp] += __shfl_xor_sync(0xffffffffu, acc[pp], 2);
            acc[pp] += __shfl_xor_sync(0xffffffffu, acc[pp], 4);
        }
        cp *= dA;
        if (ni == 0) {
            float* yp = g_y + (size_t)(rowbase + t) * DI + h * HD + pi * 4;
#pragma unroll
            for (int pp = 0; pp < 4; ++pp)
                yp[pp] = fmaf(Dval, xv[pp], acc[pp]);
        }
        if (tid == 0)
            g_cumP[(size_t)(rowbase + t) * NH + h] = cp;

        const int nxt = (cur == 2) ? 0 : cur + 1;
        if (tt + 1 < CS) {
            if (tid < 64) sx[nxt][tid] = rx;
            sB[nxt][tid] = rb;
            sC[nxt][tid] = rc;
            if (tid == 0) { ss[nxt][0] = rdt; ss[nxt][1] = rdA; }
        }
        __syncthreads();
        cur = nxt;
    }

    const size_t base = ((size_t)(dirb * NH + h) * NCH + chunk) * (HD * DS) + (size_t)tid * 64;
#pragma unroll
    for (int pp = 0; pp < 4; ++pp)
#pragma unroll
        for (int nn = 0; nn < 8; ++nn)
            *(u64t*)&g_lend[base + pp * 16 + nn * 2] = hreg[pp][nn];
}

// =====================================================================
// scan pass B (per dir)
// =====================================================================
__global__ void __launch_bounds__(256) scanB(int dir)
{
    const int bx   = blockIdx.x;
    const int b    = bx / NH;
    const int h    = bx % NH;
    const int dirb = dir * 2 + b;
    const int gid  = dirb * NH + h;
    const int rowbase = dir * M4 + b * L;
    const int tid  = threadIdx.x;

    __shared__ float pe[NCH];
    if (tid < NCH)
        pe[tid] = g_cumP[(size_t)(rowbase + tid * CS + CS - 1) * NH + h];
    __syncthreads();

    const size_t gbase = (size_t)gid * NCH * (HD * DS);
    float4 H[8];
#pragma unroll
    for (int j = 0; j < 8; ++j) H[j] = make_float4(0.f, 0.f, 0.f, 0.f);

    for (int c = 0; c < NCH; ++c) {
        const float p = pe[c];
        const size_t cb = gbase + (size_t)c * (HD * DS) + tid * 4;
        float4 v[8];
#pragma unroll
        for (int j = 0; j < 8; ++j)
            v[j] = *(const float4*)&g_lend[cb + j * 1024];
#pragma unroll
        for (int j = 0; j < 8; ++j) {
            *(float4*)&g_hcarry[cb + j * 1024] = H[j];
            H[j].x = fmaf(p, H[j].x, v[j].x);
            H[j].y = fmaf(p, H[j].y, v[j].y);
            H[j].z = fmaf(p, H[j].z, v[j].z);
            H[j].w = fmaf(p, H[j].w, v[j].w);
        }
    }
}

// =====================================================================
// scan pass C (per dir)
// =====================================================================
__global__ void __launch_bounds__(128) scanC(int dir)
{
    const int h     = blockIdx.x;
    const int chunk = blockIdx.y + 1;
    const int b     = blockIdx.z;
    const int dirb  = dir * 2 + b;
    const int tid   = threadIdx.x;
    const int ni    = tid & 7;
    const int pi    = tid >> 3;

    const int rowbase = dir * M4 + b * L;
    const int t0      = chunk * CS;

    u64t hc[4][8];
    {
        const size_t base = ((size_t)(dirb * NH + h) * NCH + chunk) * (HD * DS) + (size_t)tid * 64;
#pragma unroll
        for (int pp = 0; pp < 4; ++pp)
#pragma unroll
            for (int nn = 0; nn < 8; ++nn)
                hc[pp][nn] = *(const u64t*)&g_hcarry[base + pp * 16 + nn * 2];
    }

    for (int tt = 0; tt < CS; ++tt) {
        const int t = t0 + tt;
        const float* crow = g_xBC + (size_t)(rowbase + t) * CONVD + DI + DS + ni * 16;
        const float4 c0 = *(const float4*)(crow);
        const float4 c1 = *(const float4*)(crow + 4);
        const float4 c2 = *(const float4*)(crow + 8);
        const float4 c3 = *(const float4*)(crow + 12);
        u64t C2[8];
        C2[0] = pack2(c0.x, c0.y); C2[1] = pack2(c0.z, c0.w);
        C2[2] = pack2(c1.x, c1.y); C2[3] = pack2(c1.z, c1.w);
        C2[4] = pack2(c2.x, c2.y); C2[5] = pack2(c2.z, c2.w);
        C2[6] = pack2(c3.x, c3.y); C2[7] = pack2(c3.z, c3.w);
        u64t acc2[4] = {0ull, 0ull, 0ull, 0ull};
#pragma unroll
        for (int nn = 0; nn < 8; ++nn)
#pragma unroll
            for (int pp = 0; pp < 4; ++pp)
                acc2[pp] = fma2(hc[pp][nn], C2[nn], acc2[pp]);
        float acc[4];
#pragma unroll
        for (int pp = 0; pp < 4; ++pp) {
            float lo, hi; unpack2(acc2[pp], lo, hi);
            acc[pp] = lo + hi;
            acc[pp] += __shfl_xor_sync(0xffffffffu, acc[pp], 1);
            acc[pp] += __shfl_xor_sync(0xffffffffu, acc[pp], 2);
            acc[pp] += __shfl_xor_sync(0xffffffffu, acc[pp], 4);
        }
        if (ni == 0) {
            const float cumP = g_cumP[(size_t)(rowbase + t) * NH + h];
            float* yp = g_y + (size_t)(rowbase + t) * DI + h * HD + pi * 4;
#pragma unroll
            for (int pp = 0; pp < 4; ++pp)
                yp[pp] = fmaf(cumP, acc[pp], yp[pp]);
        }
    }
}

// =====================================================================
// gate + RMSNorm (per dir)
// =====================================================================
__global__ void __launch_bounds__(256) gatenorm_kernel(int dir, const float* __restrict__ norm_w)
{
    const int m   = blockIdx.x;
    const int row = dir * M4 + m;
    const int tid = threadIdx.x;
    const float* yrow = g_y + (size_t)row * DI;
    const float* zrow = g_zx + (size_t)row * NPROJ;

    float v[6];
    float ssum = 0.f;
#pragma unroll
    for (int i = 0; i < 6; ++i) {
        const int c = tid + i * 256;
        const float val = yrow[c] * fast_silu(zrow[c]);
        v[i] = val;
        ssum += val * val;
    }
#pragma unroll
    for (int o = 16; o > 0; o >>= 1)
        ssum += __shfl_xor_sync(0xffffffffu, ssum, o);

    __shared__ float red[8];
    if ((tid & 31) == 0) red[tid >> 5] = ssum;
    __syncthreads();
    if (tid == 0) {
        float tot = 0.f;
#pragma unroll
        for (int i = 0; i < 8; ++i) tot += red[i];
        red[0] = rsqrtf(tot / (float)DI + 1e-5f);
    }
    __syncthreads();
    const float scale = red[0];

    const int t    = m & (L - 1);
    const int dstm = dir ? (m - t + (L - 1 - t)) : m;
    __nv_bfloat16* ah = g_Ah1 + ((size_t)dir * M4 + dstm) * DI;
    __nv_bfloat16* al = g_Al1 + ((size_t)dir * M4 + dstm) * DI;

#pragma unroll
    for (int i = 0; i < 6; ++i) {
        const int c = tid + i * 256;
        const float val = v[i] * scale * norm_w[dir * DI + c];
        const __nv_bfloat16 hb = __float2bfloat16(val);
        const float lf = val - __bfloat162float(hb);
        ah[c] = hb;
        al[c] = __float2bfloat16(lf);
    }
}

// =====================================================================
// launch — fork/join pipeline (R15 schedule) + merged gemm1 at the join
// =====================================================================
extern "C" void kernel_launch(void* const* d_in, const int* in_sizes, int n_in,
                              void* d_out, int out_size)
{
    (void)in_sizes; (void)n_in; (void)out_size;
    const float* x       = (const float*)d_in[0];
    const float* in_w    = (const float*)d_in[1];
    const float* conv_w  = (const float*)d_in[2];
    const float* conv_b  = (const float*)d_in[3];
    const float* dt_bias = (const float*)d_in[4];
    const float* A_log   = (const float*)d_in[5];
    const float* Dp      = (const float*)d_in[6];
    const float* norm_w  = (const float*)d_in[7];
    const float* out_w   = (const float*)d_in[8];
    float* out = (float*)d_out;

    static cudaStream_t s1 = nullptr;
    static cudaEvent_t evFork = nullptr, evRoot = nullptr, evD1 = nullptr, evW1 = nullptr;
    if (!s1) {
        cudaStreamCreateWithFlags(&s1, cudaStreamNonBlocking);
        cudaEventCreateWithFlags(&evFork, cudaEventDisableTiming);
        cudaEventCreateWithFlags(&evRoot, cudaEventDisableTiming);
        cudaEventCreateWithFlags(&evD1, cudaEventDisableTiming);
        cudaEventCreateWithFlags(&evW1, cudaEventDisableTiming);
        cudaFuncSetAttribute((const void*)gemm0,
                             cudaFuncAttributeMaxDynamicSharedMemorySize, GSMEM);
        cudaFuncSetAttribute((const void*)gemm1,
                             cudaFuncAttributeMaxDynamicSharedMemorySize, SMEM1);
    }

    // fork s1 from the capture-origin stream BEFORE any s1 work
    cudaEventRecord(evFork, 0);
    cudaStreamWaitEvent(s1, evFork, 0);

    // s1: split w1 (only needed by gemm1)
    split_w1<<<(2 * DM * (DI / 4) + 255) / 256, 256, 0, s1>>>(out_w);
    cudaEventRecord(evW1, s1);

    // stream 0: splits needed by gemm0, then gemm0(dir0)
    split_x <<<(M4 * (DM / 4) + 255) / 256, 256>>>(x);
    split_w0<<<(2 * NPAD * (DM / 4) + 255) / 256, 256>>>(in_w);
    gemm0<<<dim3(NPAD / 128, M4 / 128), 256, GSMEM>>>(0);
    cudaEventRecord(evRoot, 0);

    // s1: dir1 pipeline
    cudaStreamWaitEvent(s1, evRoot, 0);
    gemm0<<<dim3(NPAD / 128, M4 / 128), 256, GSMEM, s1>>>(1);
    conv_kernel<<<dim3(CONVD / 256, L / 32, 2), 256, 0, s1>>>(1, conv_w, conv_b);
    dtdA_kernel<<<(M4 * NH + 255) / 256, 256, 0, s1>>>(1, dt_bias, A_log);
    scanA<<<dim3(NH, NCH, 2), 128, 0, s1>>>(1, Dp);
    scanB<<<48, 256, 0, s1>>>(1);
    scanC<<<dim3(NH, NCH - 1, 2), 128, 0, s1>>>(1);
    gatenorm_kernel<<<M4, 256, 0, s1>>>(1, norm_w);
    cudaEventRecord(evD1, s1);

    // stream 0: dir0 chain
    conv_kernel<<<dim3(CONVD / 256, L / 32, 2), 256>>>(0, conv_w, conv_b);
    dtdA_kernel<<<(M4 * NH + 255) / 256, 256>>>(0, dt_bias, A_log);
    scanA<<<dim3(NH, NCH, 2), 128>>>(0, Dp);
    scanB<<<48, 256>>>(0);
    scanC<<<dim3(NH, NCH - 1, 2), 128>>>(0);
    gatenorm_kernel<<<M4, 256>>>(0, norm_w);

    // join: merged out_proj (both dirs, single pass, writes final output)
    cudaStreamWaitEvent(0, evW1, 0);
    cudaStreamWaitEvent(0, evD1, 0);
    gemm1<<<dim3(DM / 128, M4 / 64), 256, SMEM1>>>(out);
}